// round 1
// baseline (speedup 1.0000x reference)
#include <cuda_runtime.h>

// GeGate: out = y if (0 < y <= 1) else 0, where y = x * w[col] + b[col]
// x: (B=8192, D=4096) fp32, w,b: (4096,) fp32. Pure HBM-bound elementwise.
// Strategy: float4 vectorized grid-stride loop; w/b stay L2-resident.

#define D_DIM 4096
#define D4    (D_DIM / 4)          // float4 columns per row
#define D4_MASK (D4 - 1)           // 1023

__global__ void __launch_bounds__(256) gegate_kernel(
    const float4* __restrict__ x,
    const float4* __restrict__ w,
    const float4* __restrict__ b,
    float4* __restrict__ out,
    int n4)                        // total float4 elements
{
    int stride = gridDim.x * blockDim.x;
    for (int i = blockIdx.x * blockDim.x + threadIdx.x; i < n4; i += stride) {
        int c4 = i & D4_MASK;      // float4-column within the row
        float4 xv = x[i];
        float4 wv = __ldg(&w[c4]);
        float4 bv = __ldg(&b[c4]);

        float4 y;
        y.x = fmaf(xv.x, wv.x, bv.x);
        y.y = fmaf(xv.y, wv.y, bv.y);
        y.z = fmaf(xv.z, wv.z, bv.z);
        y.w = fmaf(xv.w, wv.w, bv.w);

        y.x = (y.x > 0.0f && y.x <= 1.0f) ? y.x : 0.0f;
        y.y = (y.y > 0.0f && y.y <= 1.0f) ? y.y : 0.0f;
        y.z = (y.z > 0.0f && y.z <= 1.0f) ? y.z : 0.0f;
        y.w = (y.w > 0.0f && y.w <= 1.0f) ? y.w : 0.0f;

        out[i] = y;
    }
}

extern "C" void kernel_launch(void* const* d_in, const int* in_sizes, int n_in,
                              void* d_out, int out_size)
{
    const float4* x = (const float4*)d_in[0];
    const float4* w = (const float4*)d_in[1];
    const float4* b = (const float4*)d_in[2];
    float4* out = (float4*)d_out;

    int n4 = out_size / 4;         // 8192*4096/4 = 8388608 float4s

    // One float4 per thread per iteration; size grid so each thread does ~4
    // iterations (keeps grid modest, good locality, full occupancy).
    const int threads = 256;
    int blocks = (n4 + threads * 4 - 1) / (threads * 4);   // ~8192 blocks
    gegate_kernel<<<blocks, threads>>>(x, w, b, out, n4);
}